// round 2
// baseline (speedup 1.0000x reference)
#include <cuda_runtime.h>
#include <cstdint>

// Attention: (B,H,S,D) = (256,32,16,64), scale 1/sqrt(8), +ones mask, softmax,
// JAX threefry dropout (key 42, p_keep=0.7, partitionable mode, XOR-folded words), @V.

#define NBLK 8192            // B*H
#define TPB  256             // S*S threads: one score element per thread

#define TF_ROUND(r) { x0 += x1; x1 = __funnelshift_l(x1, x1, (r)); x1 ^= x0; }

// JAX threefry2x32 with key (0, 42), counter (hi=0, lo=idx); partitionable-mode
// 32-bit draw = out1 ^ out2 (XOR fold of the two output words).
static __device__ __forceinline__ uint32_t jax_threefry_bits(uint32_t idx) {
    const uint32_t k0 = 0u, k1 = 42u, k2 = 0u ^ 42u ^ 0x1BD11BDAu;
    uint32_t x0 = 0u + k0;        // c_hi + ks[0]
    uint32_t x1 = idx + k1;       // c_lo + ks[1]
    TF_ROUND(13) TF_ROUND(15) TF_ROUND(26) TF_ROUND(6)
    x0 += k1; x1 += k2 + 1u;
    TF_ROUND(17) TF_ROUND(29) TF_ROUND(16) TF_ROUND(24)
    x0 += k2; x1 += k0 + 2u;
    TF_ROUND(13) TF_ROUND(15) TF_ROUND(26) TF_ROUND(6)
    x0 += k0; x1 += k1 + 3u;
    TF_ROUND(17) TF_ROUND(29) TF_ROUND(16) TF_ROUND(24)
    x0 += k1; x1 += k2 + 4u;
    TF_ROUND(13) TF_ROUND(15) TF_ROUND(26) TF_ROUND(6)
    x0 += k2; x1 += k0 + 5u;
    return x0 ^ x1;               // XOR fold (partitionable, bit_width<=32)
}

__global__ __launch_bounds__(TPB) void attn_drop_kernel(
    const float4* __restrict__ qg,
    const float4* __restrict__ kg,
    const float4* __restrict__ vg,
    float4* __restrict__ og)
{
    __shared__ float4 sq[16 * 16];      // q[s][d4]
    __shared__ float4 sk[16 * 17];      // k[t][d4], padded row stride 17
    __shared__ float4 sv[16 * 16];      // v[u][d4]
    __shared__ float  sattn[16 * 17];   // attn[s][t], padded

    const int bh  = blockIdx.x;
    const int tid = threadIdx.x;
    const int row = tid >> 4;           // s (scores) / s (out)
    const int col = tid & 15;           // t (scores) / d4 (out)
    const int base = bh * 256;          // float4 tile offset (16*64/4)

    sq[tid]             = qg[base + tid];
    sk[row * 17 + col]  = kg[base + tid];
    sv[tid]             = vg[base + tid];
    __syncthreads();

    // ---- scores: attn[row][col] = q[row] . k[col] * scale + 1 ----
    float acc = 0.0f;
    #pragma unroll
    for (int i = 0; i < 16; ++i) {
        float4 a = sq[row * 16 + i];
        float4 b = sk[col * 17 + i];
        acc += a.x * b.x + a.y * b.y + a.z * b.z + a.w * b.w;
    }
    float sc = acc * 0.35355339059327373f + 1.0f;

    // ---- softmax over col (16 lanes of a half-warp) ----
    float m = sc;
    #pragma unroll
    for (int o = 8; o; o >>= 1)
        m = fmaxf(m, __shfl_xor_sync(0xffffffffu, m, o, 16));
    float e = __expf(sc - m);
    float ssum = e;
    #pragma unroll
    for (int o = 8; o; o >>= 1)
        ssum += __shfl_xor_sync(0xffffffffu, ssum, o, 16);
    float p = e / ssum;

    // ---- dropout: JAX threefry, element index in (B,H,S,S) row-major ----
    uint32_t idx  = (uint32_t)bh * 256u + (uint32_t)tid;
    uint32_t bits = jax_threefry_bits(idx);
    float u = __uint_as_float((bits >> 9) | 0x3f800000u) - 1.0f;
    p = (u < 0.7f) ? (p / 0.7f) : 0.0f;

    sattn[row * 17 + col] = p;
    __syncthreads();

    // ---- out[row][4*col .. 4*col+3] = sum_u attn[row][u] * v[u][...] ----
    float4 o4 = make_float4(0.f, 0.f, 0.f, 0.f);
    #pragma unroll
    for (int u_ = 0; u_ < 16; ++u_) {
        float  a  = sattn[row * 17 + u_];
        float4 vv = sv[u_ * 16 + col];
        o4.x += a * vv.x;
        o4.y += a * vv.y;
        o4.z += a * vv.z;
        o4.w += a * vv.w;
    }
    og[base + tid] = o4;
}

extern "C" void kernel_launch(void* const* d_in, const int* in_sizes, int n_in,
                              void* d_out, int out_size) {
    attn_drop_kernel<<<NBLK, TPB>>>(
        (const float4*)d_in[0],   // q
        (const float4*)d_in[1],   // k
        (const float4*)d_in[2],   // v
        (float4*)d_out);
}

// round 3
// speedup vs baseline: 1.3637x; 1.3637x over previous
#include <cuda_runtime.h>
#include <cstdint>

// Attention: (B,H,S,D) = (256,32,16,64), scale 1/sqrt(8), +ones mask, softmax,
// JAX threefry dropout (key 42, p_keep=0.7, partitionable, XOR-folded), @V.
// 2x2-tiled: 64 threads/head, 4 heads per 256-thread CTA.

#define TPB 256
#define HEADS_PER_CTA 4
#define NBLK (8192 / HEADS_PER_CTA)

#define TF_ROUND(r) { x0 += x1; x1 = __funnelshift_l(x1, x1, (r)); x1 ^= x0; }

// JAX threefry2x32, key (0,42), counter (0, idx); partitionable 32-bit draw = out0^out1.
static __device__ __forceinline__ uint32_t jax_threefry_bits(uint32_t idx) {
    const uint32_t k0 = 0u, k1 = 42u, k2 = 0u ^ 42u ^ 0x1BD11BDAu;
    uint32_t x0 = 0u + k0;
    uint32_t x1 = idx + k1;
    TF_ROUND(13) TF_ROUND(15) TF_ROUND(26) TF_ROUND(6)
    x0 += k1; x1 += k2 + 1u;
    TF_ROUND(17) TF_ROUND(29) TF_ROUND(16) TF_ROUND(24)
    x0 += k2; x1 += k0 + 2u;
    TF_ROUND(13) TF_ROUND(15) TF_ROUND(26) TF_ROUND(6)
    x0 += k0; x1 += k1 + 3u;
    TF_ROUND(17) TF_ROUND(29) TF_ROUND(16) TF_ROUND(24)
    x0 += k1; x1 += k2 + 4u;
    TF_ROUND(13) TF_ROUND(15) TF_ROUND(26) TF_ROUND(6)
    x0 += k2; x1 += k0 + 5u;
    return x0 ^ x1;
}

static __device__ __forceinline__ float drop_scale(uint32_t idx) {
    uint32_t bits = jax_threefry_bits(idx);
    float u = __uint_as_float((bits >> 9) | 0x3f800000u) - 1.0f;
    return (u < 0.7f) ? (1.0f / 0.7f) : 0.0f;
}

static __device__ __forceinline__ float dot4(float4 a, float4 b) {
    return a.x * b.x + a.y * b.y + a.z * b.z + a.w * b.w;
}

__global__ __launch_bounds__(TPB) void attn_drop_kernel(
    const float4* __restrict__ qg,
    const float4* __restrict__ kg,
    const float4* __restrict__ vg,
    float4* __restrict__ og)
{
    __shared__ float4 sq[HEADS_PER_CTA][16 * 17];   // [h][s*17 + d4], padded
    __shared__ float4 sk[HEADS_PER_CTA][16 * 17];   // [h][t*17 + d4], padded
    __shared__ float4 sv[HEADS_PER_CTA][16 * 16];   // [h][u*16 + d4]
    __shared__ float  sattn[HEADS_PER_CTA][16 * 17];

    const int tid = threadIdx.x;
    const int blk = blockIdx.x;
    const int base_blk = blk * (HEADS_PER_CTA * 256);   // float4 offset

    // ---- cooperative load of 4 heads ----
    #pragma unroll
    for (int i = tid; i < HEADS_PER_CTA * 256; i += TPB) {
        int h_  = i >> 8;
        int loc = i & 255;
        int r = loc >> 4, c = loc & 15;
        sq[h_][r * 17 + c] = qg[base_blk + i];
        sk[h_][r * 17 + c] = kg[base_blk + i];
        sv[h_][loc]        = vg[base_blk + i];
    }
    __syncthreads();

    const int h   = tid >> 6;
    const int t64 = tid & 63;
    const int r2  = t64 >> 3;          // row pair id 0..7
    const int c2  = t64 & 7;           // col id 0..7
    const int r0  = r2 * 2, r1 = r0 + 1;
    const int cA  = c2, cB = c2 + 8;
    const int bh  = blk * HEADS_PER_CTA + h;
    const int base = bh * 256;

    // ---- scores: 2x2 block ----
    float s00 = 0.f, s01 = 0.f, s10 = 0.f, s11 = 0.f;
    #pragma unroll
    for (int i = 0; i < 16; ++i) {
        float4 a0 = sq[h][r0 * 17 + i];
        float4 a1 = sq[h][r1 * 17 + i];
        float4 b0 = sk[h][cA * 17 + i];
        float4 b1 = sk[h][cB * 17 + i];
        s00 += dot4(a0, b0);  s01 += dot4(a0, b1);
        s10 += dot4(a1, b0);  s11 += dot4(a1, b1);
    }
    const float SCALE = 0.35355339059327373f;
    s00 = s00 * SCALE + 1.0f;  s01 = s01 * SCALE + 1.0f;
    s10 = s10 * SCALE + 1.0f;  s11 = s11 * SCALE + 1.0f;

    // ---- softmax over each row (8 lanes x 2 cols each) ----
    float m0 = fmaxf(s00, s01), m1 = fmaxf(s10, s11);
    #pragma unroll
    for (int o = 4; o; o >>= 1) {
        m0 = fmaxf(m0, __shfl_xor_sync(0xffffffffu, m0, o, 8));
        m1 = fmaxf(m1, __shfl_xor_sync(0xffffffffu, m1, o, 8));
    }
    float e00 = __expf(s00 - m0), e01 = __expf(s01 - m0);
    float e10 = __expf(s10 - m1), e11 = __expf(s11 - m1);
    float t0 = e00 + e01, t1 = e10 + e11;
    #pragma unroll
    for (int o = 4; o; o >>= 1) {
        t0 += __shfl_xor_sync(0xffffffffu, t0, o, 8);
        t1 += __shfl_xor_sync(0xffffffffu, t1, o, 8);
    }
    float inv0 = 1.0f / t0, inv1 = 1.0f / t1;

    // ---- dropout (element index in (B,H,S,S) row-major) ----
    uint32_t ib = (uint32_t)base + (uint32_t)(r0 * 16 + c2);
    float p00 = e00 * inv0 * drop_scale(ib);
    float p01 = e01 * inv0 * drop_scale(ib + 8u);
    float p10 = e10 * inv1 * drop_scale(ib + 16u);
    float p11 = e11 * inv1 * drop_scale(ib + 24u);

    sattn[h][r0 * 17 + cA] = p00;
    sattn[h][r0 * 17 + cB] = p01;
    sattn[h][r1 * 17 + cA] = p10;
    sattn[h][r1 * 17 + cB] = p11;
    __syncwarp();   // attn rows produced & consumed within the same warp

    // ---- AV: out rows r0,r1 x col4s cA,cB ----
    float4 o00 = make_float4(0,0,0,0), o01 = make_float4(0,0,0,0);
    float4 o10 = make_float4(0,0,0,0), o11 = make_float4(0,0,0,0);
    #pragma unroll
    for (int u = 0; u < 16; ++u) {
        float  a0 = sattn[h][r0 * 17 + u];
        float  a1 = sattn[h][r1 * 17 + u];
        float4 v0 = sv[h][u * 16 + cA];
        float4 v1 = sv[h][u * 16 + cB];
        o00.x += a0*v0.x; o00.y += a0*v0.y; o00.z += a0*v0.z; o00.w += a0*v0.w;
        o01.x += a0*v1.x; o01.y += a0*v1.y; o01.z += a0*v1.z; o01.w += a0*v1.w;
        o10.x += a1*v0.x; o10.y += a1*v0.y; o10.z += a1*v0.z; o10.w += a1*v0.w;
        o11.x += a1*v1.x; o11.y += a1*v1.y; o11.z += a1*v1.z; o11.w += a1*v1.w;
    }
    og[base + r0 * 16 + cA] = o00;
    og[base + r0 * 16 + cB] = o01;
    og[base + r1 * 16 + cA] = o10;
    og[base + r1 * 16 + cB] = o11;
}

extern "C" void kernel_launch(void* const* d_in, const int* in_sizes, int n_in,
                              void* d_out, int out_size) {
    attn_drop_kernel<<<NBLK, TPB>>>(
        (const float4*)d_in[0],   // q
        (const float4*)d_in[1],   // k
        (const float4*)d_in[2],   // v
        (float4*)d_out);
}